// round 12
// baseline (speedup 1.0000x reference)
#include <cuda_runtime.h>
#include <cuda_bf16.h>
#include <math.h>
#include <stdint.h>

#define NN   50000      // nodes
#define NE   600000     // edges
#define NEL  (NE + NN)  // edges + self loops
#define NG   100        // graphs
#define OUTC 64
#define DEMO 8

#define NTILES ((NN + 127) / 128)        // 391

#define SCAN_BLK  1024
#define SCAN_NBLK ((NN + SCAN_BLK - 1) / SCAN_BLK)   // 49

// W interleaved chunks (uint4): L1 8*128*4=4096, L2 4096, L3 8*64*4=2048
#define WC_L2 4096
#define WC_L3 8192
#define WC_TOT 10240

#define KS 136          // smem A-tile row stride in bf16 (272 B -> conflict-free)

// ---------------- scratch (device globals; zero-init at load; no allocation) ----------------
__device__ __nv_bfloat16 g_Xb[(size_t)NN * 128];    // bf16 input features
__device__ __nv_bfloat16 g_Ab[(size_t)NN * 128];    // layer output bf16 (layers 1,2)
__device__ float g_A[(size_t)NN * OUTC];            // final layer fp32 (for pooling)
__device__ uint4 g_Wint[WC_TOT];                    // interleaved W fragments (hi/lo)
__device__ int   g_deg[NN];                         // self-zeroed each call by k_scan1
__device__ int   g_rowptr[NN + 1];
__device__ int   g_cursor[NN];
__device__ int   g_csrsrc[NEL];                     // src only; norm recomputed by consumer
__device__ float g_dinv[NN];
__device__ int   g_bsum[SCAN_NBLK];

// ================= fp32 -> bf16 hi/lo split =================
__device__ __forceinline__ void split_bf16(float v, unsigned short& h, unsigned short& l) {
    __nv_bfloat16 hb = __float2bfloat16(v);
    __nv_bfloat16 lb = __float2bfloat16(v - __bfloat162float(hb));
    h = __bfloat16_as_ushort(hb);
    l = __bfloat16_as_ushort(lb);
}

// fused prep: edge degree count + x->bf16 + W interleave/split. Independent elementwise parts.
__global__ void k_prep(const float* __restrict__ x,
                       const float* __restrict__ W1, const float* __restrict__ W2,
                       const float* __restrict__ W3, const int* __restrict__ dst) {
    int i = blockIdx.x * blockDim.x + threadIdx.x;

    if (i < NE) atomicAdd(&g_deg[dst[i]], 1);       // deg starts 0 (zeroed by prior scan1)

    if (i < WC_TOT * 4) {                            // one word of one W chunk
        int c = i >> 2, s = i & 3;
        const float* Wsrc; int Ncols; int cl = c;
        if (cl < WC_L2)      { Wsrc = W1; Ncols = 128; }
        else if (cl < WC_L3) { Wsrc = W2; Ncols = 128; cl -= WC_L2; }
        else                 { Wsrc = W3; Ncols = 64;  cl -= WC_L3; }
        int q = cl & 3, rest = cl >> 2;
        int n = rest % Ncols, k08 = rest / Ncols;
        int kb = k08 * 16 + 2 * q + ((s & 1) ? 8 : 0);
        float v0 = Wsrc[kb * Ncols + n];
        float v1 = Wsrc[(kb + 1) * Ncols + n];
        unsigned short h0, l0, h1, l1;
        split_bf16(v0, h0, l0);
        split_bf16(v1, h1, l1);
        uint32_t w = (s < 2) ? ((uint32_t)h0 | ((uint32_t)h1 << 16))
                             : ((uint32_t)l0 | ((uint32_t)l1 << 16));
        ((uint32_t*)g_Wint)[i] = w;
    }

    if (i < NN * 32) {                               // x: one float4 -> 4 bf16
        float4 v = ((const float4*)x)[i];
        __nv_bfloat16 b0 = __float2bfloat16(v.x), b1 = __float2bfloat16(v.y);
        __nv_bfloat16 b2 = __float2bfloat16(v.z), b3 = __float2bfloat16(v.w);
        uint2 u;
        u.x = (uint32_t)__bfloat16_as_ushort(b0) | ((uint32_t)__bfloat16_as_ushort(b1) << 16);
        u.y = (uint32_t)__bfloat16_as_ushort(b2) | ((uint32_t)__bfloat16_as_ushort(b3) << 16);
        ((uint2*)g_Xb)[i] = u;
    }
}

// ---------------- scan phase 1: block-local inclusive scan of (deg+1); self-zero deg ----------------
__global__ void k_scan1() {
    __shared__ int wsum[32];
    int t = threadIdx.x, lane = t & 31, w = t >> 5;
    int idx = blockIdx.x * SCAN_BLK + t;
    int v = 0;
    if (idx < NN) {
        int d = g_deg[idx];
        g_deg[idx] = 0;                      // reset for next graph replay
        v = d + 1;                           // + self loop
        g_dinv[idx] = rsqrtf((float)v);
    }
    int x = v;
    #pragma unroll
    for (int o = 1; o < 32; o <<= 1) {
        int y = __shfl_up_sync(0xFFFFFFFFu, x, o);
        if (lane >= o) x += y;
    }
    if (lane == 31) wsum[w] = x;
    __syncthreads();
    if (w == 0) {
        int s = wsum[lane];
        #pragma unroll
        for (int o = 1; o < 32; o <<= 1) {
            int y = __shfl_up_sync(0xFFFFFFFFu, s, o);
            if (lane >= o) s += y;
        }
        wsum[lane] = s;
    }
    __syncthreads();
    int incl = x + (w > 0 ? wsum[w - 1] : 0);
    if (idx < NN) g_rowptr[idx + 1] = incl;
    if (t == SCAN_BLK - 1) g_bsum[blockIdx.x] = incl;
}

// scan phase 3 (with inlined phase-2 scan of 49 block sums) + cursor init
__global__ void k_scan3() {
    __shared__ int sboff[SCAN_NBLK];
    int t = threadIdx.x;
    if (t < 32) {
        int i0 = 2 * t, i1 = 2 * t + 1;
        int e0 = (i0 < SCAN_NBLK) ? g_bsum[i0] : 0;
        int e1 = (i1 < SCAN_NBLK) ? g_bsum[i1] : 0;
        int p = e0 + e1, x = p;
        #pragma unroll
        for (int o = 1; o < 32; o <<= 1) {
            int y = __shfl_up_sync(0xFFFFFFFFu, x, o);
            if (t >= o) x += y;
        }
        int excl = x - p;
        if (i0 < SCAN_NBLK) sboff[i0] = excl;
        if (i1 < SCAN_NBLK) sboff[i1] = excl + e0;
    }
    __syncthreads();
    int i = blockIdx.x * blockDim.x + t;
    if (i >= NN) return;
    int r = g_rowptr[i + 1] + sboff[i >> 10];
    g_rowptr[i + 1] = r;
    if (i + 1 < NN) g_cursor[i + 1] = r;
    if (i == 0) { g_rowptr[0] = 0; g_cursor[0] = 0; }
}

// slim CSR fill: src index only (4 B payload, no dinv loads)
__global__ void k_fill_csr(const int* __restrict__ src, const int* __restrict__ dst) {
    int i = blockIdx.x * blockDim.x + threadIdx.x;
    if (i >= NEL) return;
    int s, d;
    if (i < NE) { s = src[i]; d = dst[i]; }
    else        { s = d = i - NE; }
    int pos = atomicAdd(&g_cursor[d], 1);
    g_csrsrc[pos] = s;
}

// ================= HMMA bf16 m16n8k16 =================
__device__ __forceinline__ void mma_bf16(float* c, const uint32_t* a, uint32_t b0, uint32_t b1) {
    asm volatile(
        "mma.sync.aligned.m16n8k16.row.col.f32.bf16.bf16.f32 "
        "{%0,%1,%2,%3}, {%4,%5,%6,%7}, {%8,%9}, {%0,%1,%2,%3};"
        : "+f"(c[0]), "+f"(c[1]), "+f"(c[2]), "+f"(c[3])
        : "r"(a[0]), "r"(a[1]), "r"(a[2]), "r"(a[3]), "r"(b0), "r"(b1));
}

// ====== FUSED per-128-row-tile:  sA = S @ X (agg, smem) ; Out = relu(sA @ (Whi+Wlo)T + b) ======
// 256 thr = 8 warps; each warp aggregates 16 nodes into smem, then does its MMA rows from smem.
template <int N, bool F32OUT>
__global__ __launch_bounds__(256)
void k_fused(const __nv_bfloat16* __restrict__ X, const uint4* __restrict__ Wc,
             const float* __restrict__ bias, void* __restrict__ Out) {
    constexpr int NT = N / 8;
    constexpr int NCH = 32 * N;                // W chunks: 8*N*4
    extern __shared__ char smem[];
    uint4* sW = (uint4*)smem;
    __nv_bfloat16* sA = (__nv_bfloat16*)(smem + NCH * 16);   // [128][KS]

    int tid = threadIdx.x, wid = tid >> 5, ln = tid & 31;

    // stage W
    #pragma unroll
    for (int i = tid; i < NCH; i += 256) sW[i] = Wc[i];

    // ---- phase 1: aggregate this tile's 16 rows per warp into sA ----
    int row0w = wid * 16;
    int nodebase = blockIdx.x * 128 + row0w;
    // prefetch rowptr[nodebase..nodebase+16] and dinv via lanes + shfl
    int idxl = nodebase + ln;
    int rp = g_rowptr[(idxl <= NN) ? idxl : NN];
    float dvl = (idxl < NN) ? g_dinv[idxl] : 0.f;

    for (int r = 0; r < 16; r++) {
        int beg = __shfl_sync(0xFFFFFFFFu, rp, r);
        int end = __shfl_sync(0xFFFFFFFFu, rp, r + 1);
        float dinv_d = __shfl_sync(0xFFFFFFFFu, dvl, r);
        float4 acc = make_float4(0.f, 0.f, 0.f, 0.f);

        int e = beg;
        for (; e + 4 <= end; e += 4) {
            int s0 = g_csrsrc[e + 0], s1 = g_csrsrc[e + 1];
            int s2 = g_csrsrc[e + 2], s3 = g_csrsrc[e + 3];
            float w0 = dinv_d * g_dinv[s0], w1 = dinv_d * g_dinv[s1];
            float w2 = dinv_d * g_dinv[s2], w3 = dinv_d * g_dinv[s3];
            uint2 u0 = ((const uint2*)(X + (size_t)s0 * 128))[ln];
            uint2 u1 = ((const uint2*)(X + (size_t)s1 * 128))[ln];
            uint2 u2 = ((const uint2*)(X + (size_t)s2 * 128))[ln];
            uint2 u3 = ((const uint2*)(X + (size_t)s3 * 128))[ln];
            float2 a0 = __bfloat1622float2(*(__nv_bfloat162*)&u0.x);
            float2 c0 = __bfloat1622float2(*(__nv_bfloat162*)&u0.y);
            float2 a1 = __bfloat1622float2(*(__nv_bfloat162*)&u1.x);
            float2 c1 = __bfloat1622float2(*(__nv_bfloat162*)&u1.y);
            float2 a2 = __bfloat1622float2(*(__nv_bfloat162*)&u2.x);
            float2 c2 = __bfloat1622float2(*(__nv_bfloat162*)&u2.y);
            float2 a3 = __bfloat1622float2(*(__nv_bfloat162*)&u3.x);
            float2 c3 = __bfloat1622float2(*(__nv_bfloat162*)&u3.y);
            acc.x = fmaf(w0, a0.x, acc.x); acc.y = fmaf(w0, a0.y, acc.y);
            acc.z = fmaf(w0, c0.x, acc.z); acc.w = fmaf(w0, c0.y, acc.w);
            acc.x = fmaf(w1, a1.x, acc.x); acc.y = fmaf(w1, a1.y, acc.y);
            acc.z = fmaf(w1, c1.x, acc.z); acc.w = fmaf(w1, c1.y, acc.w);
            acc.x = fmaf(w2, a2.x, acc.x); acc.y = fmaf(w2, a2.y, acc.y);
            acc.z = fmaf(w2, c2.x, acc.z); acc.w = fmaf(w2, c2.y, acc.w);
            acc.x = fmaf(w3, a3.x, acc.x); acc.y = fmaf(w3, a3.y, acc.y);
            acc.z = fmaf(w3, c3.x, acc.z); acc.w = fmaf(w3, c3.y, acc.w);
        }
        for (; e < end; e++) {
            int s = g_csrsrc[e];
            float w = dinv_d * g_dinv[s];
            uint2 u = ((const uint2*)(X + (size_t)s * 128))[ln];
            float2 a = __bfloat1622float2(*(__nv_bfloat162*)&u.x);
            float2 c = __bfloat1622float2(*(__nv_bfloat162*)&u.y);
            acc.x = fmaf(w, a.x, acc.x); acc.y = fmaf(w, a.y, acc.y);
            acc.z = fmaf(w, c.x, acc.z); acc.w = fmaf(w, c.y, acc.w);
        }

        __nv_bfloat162 p01 = __floats2bfloat162_rn(acc.x, acc.y);
        __nv_bfloat162 p23 = __floats2bfloat162_rn(acc.z, acc.w);
        uint2 u;
        u.x = *(uint32_t*)&p01;
        u.y = *(uint32_t*)&p23;
        ((uint2*)(sA + (size_t)(row0w + r) * KS))[ln] = u;
    }
    __syncthreads();

    // ---- phase 2: MMA from smem A-tile ----
    int grp = ln >> 2;                         // 0..7
    int q   = ln & 3;
    int qk  = q * 2;

    float acc[NT][4];
    #pragma unroll
    for (int j = 0; j < NT; j++)
        #pragma unroll
        for (int p = 0; p < 4; p++) acc[j][p] = 0.f;

    #pragma unroll
    for (int k08 = 0; k08 < 8; k08++) {
        const __nv_bfloat16* ap = sA + (size_t)(row0w + grp) * KS + k08 * 16 + qk;
        uint32_t a[4];
        a[0] = *(const uint32_t*)(ap);
        a[1] = *(const uint32_t*)(ap + 8 * KS);
        a[2] = *(const uint32_t*)(ap + 8);
        a[3] = *(const uint32_t*)(ap + 8 * KS + 8);

        #pragma unroll
        for (int j = 0; j < NT; j++) {
            uint4 bb = sW[(k08 * N + j * 8 + grp) * 4 + q];   // one LDS.128
            mma_bf16(acc[j], a, bb.x, bb.y);   // A * W_hi
            mma_bf16(acc[j], a, bb.z, bb.w);   // A * W_lo
        }
    }

    int rc = blockIdx.x * 128 + row0w + grp;
    int cc = q * 2;
    #pragma unroll
    for (int j = 0; j < NT; j++) {
        int col = j * 8 + cc;
        float bx = bias[col], by = bias[col + 1];
        float v0 = fmaxf(acc[j][0] + bx, 0.f), v1 = fmaxf(acc[j][1] + by, 0.f);
        float v2 = fmaxf(acc[j][2] + bx, 0.f), v3 = fmaxf(acc[j][3] + by, 0.f);
        if (F32OUT) {
            float* O = (float*)Out;
            if (rc < NN)     *(float2*)&O[(size_t)rc * N + col]       = make_float2(v0, v1);
            if (rc + 8 < NN) *(float2*)&O[(size_t)(rc + 8) * N + col] = make_float2(v2, v3);
        } else {
            __nv_bfloat16* O = (__nv_bfloat16*)Out;
            if (rc < NN) {
                __nv_bfloat162 h = __floats2bfloat162_rn(v0, v1);
                *(uint32_t*)&O[(size_t)rc * N + col] = *(uint32_t*)&h;
            }
            if (rc + 8 < NN) {
                __nv_bfloat162 h = __floats2bfloat162_rn(v2, v3);
                *(uint32_t*)&O[(size_t)(rc + 8) * N + col] = *(uint32_t*)&h;
            }
        }
    }
}

// ---------------- fused mean-pool (batch is sorted) + MLP head ----------------
__device__ __forceinline__ int lower_bound_batch(const int* __restrict__ batch, int key) {
    int lo = 0, hi = NN;
    while (lo < hi) {
        int mid = (lo + hi) >> 1;
        if (batch[mid] < key) lo = mid + 1; else hi = mid;
    }
    return lo;
}

__global__ __launch_bounds__(256)
void k_pool_mlp(const float* __restrict__ A, const int* __restrict__ batch,
                const float* __restrict__ demo,
                const float* __restrict__ Wf1, const float* __restrict__ bf1,
                const float* __restrict__ Wf2, const float* __restrict__ bf2,
                const float* __restrict__ Wf3, const float* __restrict__ bf3,
                float* __restrict__ out) {
    int g = blockIdx.x;
    int t = threadIdx.x;
    __shared__ int s_beg, s_end;
    __shared__ float sp[4][64];
    __shared__ float z[72];
    __shared__ float z1[64];
    __shared__ float z2[32];

    if (t == 0) s_beg = lower_bound_batch(batch, g);
    if (t == 1) s_end = lower_bound_batch(batch, g + 1);
    __syncthreads();
    int beg = s_beg, end = s_end;

    int c = t & 63, rg = t >> 6;
    float acc = 0.f;
    for (int r = beg + rg; r < end; r += 4)
        acc += A[(size_t)r * OUTC + c];
    sp[rg][c] = acc;
    __syncthreads();

    if (t < 64) {
        float s = sp[0][t] + sp[1][t] + sp[2][t] + sp[3][t];
        float invc = 1.f / fmaxf((float)(end - beg), 1.f);
        z[t] = s * invc;
    }
    if (t < DEMO) z[64 + t] = demo[g * DEMO + t];
    __syncthreads();

    if (t < 64) {
        float a = bf1[t];
        #pragma unroll 8
        for (int k = 0; k < 72; k++) a += z[k] * Wf1[k * 64 + t];
        z1[t] = fmaxf(a, 0.f);
    }
    __syncthreads();
    if (t < 32) {
        float a = bf2[t];
        #pragma unroll 8
        for (int k = 0; k < 64; k++) a += z1[k] * Wf2[k * 32 + t];
        z2[t] = fmaxf(a, 0.f);
    }
    __syncthreads();
    if (t < 2) {
        float a = bf3[t];
        #pragma unroll
        for (int k = 0; k < 32; k++) a += z2[k] * Wf3[k * 2 + t];
        out[g * 2 + t] = a;
    }
}

// ---------------- launch ----------------
extern "C" void kernel_launch(void* const* d_in, const int* in_sizes, int n_in,
                              void* d_out, int out_size) {
    const float* x     = (const float*)d_in[0];
    const int*   ei    = (const int*)  d_in[1];   // [2, NE]
    const int*   batch = (const int*)  d_in[2];
    const float* demo  = (const float*)d_in[3];
    const float* W1 = (const float*)d_in[4];  const float* b1 = (const float*)d_in[5];
    const float* W2 = (const float*)d_in[6];  const float* b2 = (const float*)d_in[7];
    const float* W3 = (const float*)d_in[8];  const float* b3 = (const float*)d_in[9];
    const float* Wf1 = (const float*)d_in[10]; const float* bf1 = (const float*)d_in[11];
    const float* Wf2 = (const float*)d_in[12]; const float* bf2 = (const float*)d_in[13];
    const float* Wf3 = (const float*)d_in[14]; const float* bf3 = (const float*)d_in[15];
    float* out = (float*)d_out;

    const int* src = ei;
    const int* dst = ei + NE;

    float* A;
    __nv_bfloat16 *Xb, *Ab;
    uint4* Wc;
    cudaGetSymbolAddress((void**)&A,  g_A);
    cudaGetSymbolAddress((void**)&Xb, g_Xb);
    cudaGetSymbolAddress((void**)&Ab, g_Ab);
    cudaGetSymbolAddress((void**)&Wc, g_Wint);

    const int SA_BYTES = 128 * KS * 2;                 // 34816
    const int SMEM128 = 32 * 128 * 16 + SA_BYTES;      // 100352
    const int SMEM64  = 32 * 64  * 16 + SA_BYTES;      //  67584
    cudaFuncSetAttribute(k_fused<128, false>, cudaFuncAttributeMaxDynamicSharedMemorySize, SMEM128);
    cudaFuncSetAttribute(k_fused<64,  true>,  cudaFuncAttributeMaxDynamicSharedMemorySize, SMEM64);

    const int T = 256;
    // --- fused prep (deg atomics + x->bf16 + W interleave) ---
    k_prep<<<(NN * 32 + T - 1) / T, T>>>(x, W1, W2, W3, dst);
    // --- CSR build ---
    k_scan1<<<SCAN_NBLK, SCAN_BLK>>>();
    k_scan3<<<(NN + T - 1) / T, T>>>();
    k_fill_csr<<<(NEL + T - 1) / T, T>>>(src, dst);

    // --- 3 fused agg+GEMM layers ---
    k_fused<128, false><<<NTILES, 256, SMEM128>>>(Xb, Wc, b1, Ab);
    k_fused<128, false><<<NTILES, 256, SMEM128>>>(Ab, Wc + WC_L2, b2, Ab);
    k_fused<64,  true><<<NTILES, 256, SMEM64>>>(Ab, Wc + WC_L3, b3, A);

    // --- fused pooling + MLP head ---
    k_pool_mlp<<<NG, 256>>>(A, batch, demo, Wf1, bf1, Wf2, bf2, Wf3, bf3, out);
}

// round 13
// speedup vs baseline: 1.4985x; 1.4985x over previous
#include <cuda_runtime.h>
#include <cuda_bf16.h>
#include <math.h>
#include <stdint.h>

#define NN   50000      // nodes
#define NE   600000     // edges
#define NEL  (NE + NN)  // edges + self loops
#define NG   100        // graphs
#define OUTC 64
#define DEMO 8

#define NTILES ((NN + 127) / 128)        // 391
#define NPAD   (NTILES * 128)            // 50048

#define SCAN_BLK  1024
#define SCAN_NBLK ((NN + SCAN_BLK - 1) / SCAN_BLK)   // 49

// W interleaved chunks (uint4): L1 8*128*4=4096, L2 4096, L3 8*64*4=2048
#define WC_L2 4096
#define WC_L3 8192
#define WC_TOT 10240

// ---------------- scratch (device globals; zero-init at load; no allocation) ----------------
__device__ __nv_bfloat16 g_Xb[(size_t)NN * 128];    // bf16 input features
__device__ __nv_bfloat16 g_Ab[(size_t)NN * 128];    // GEMM bf16 output (layers 1,2)
__device__ __nv_bfloat16 g_G[(size_t)NPAD * 128];   // agg output = GEMM input; pad rows stay 0
__device__ float g_A[(size_t)NN * OUTC];            // final layer fp32 (for pooling)
__device__ uint4 g_Wint[WC_TOT];                    // interleaved W fragments (hi/lo)
__device__ int   g_deg[NN];                         // self-zeroed each call by k_scan1
__device__ int   g_rowptr[NN + 1];
__device__ int   g_cursor[NN];
__device__ int2  g_csr[NEL];                        // {src, norm_bits}
__device__ float g_dinv[NN];
__device__ int   g_bsum[SCAN_NBLK];

// ================= fp32 -> bf16 hi/lo split =================
__device__ __forceinline__ void split_bf16(float v, unsigned short& h, unsigned short& l) {
    __nv_bfloat16 hb = __float2bfloat16(v);
    __nv_bfloat16 lb = __float2bfloat16(v - __bfloat162float(hb));
    h = __bfloat16_as_ushort(hb);
    l = __bfloat16_as_ushort(lb);
}

// fused prep: edge degree count + x->bf16 + W interleave/split. Independent elementwise parts.
__global__ void k_prep(const float* __restrict__ x,
                       const float* __restrict__ W1, const float* __restrict__ W2,
                       const float* __restrict__ W3, const int* __restrict__ dst) {
    int i = blockIdx.x * blockDim.x + threadIdx.x;

    if (i < NE) atomicAdd(&g_deg[dst[i]], 1);       // deg starts 0 (zeroed by prior scan1)

    if (i < WC_TOT * 4) {                            // one word of one W chunk
        int c = i >> 2, s = i & 3;
        const float* Wsrc; int Ncols; int cl = c;
        if (cl < WC_L2)      { Wsrc = W1; Ncols = 128; }
        else if (cl < WC_L3) { Wsrc = W2; Ncols = 128; cl -= WC_L2; }
        else                 { Wsrc = W3; Ncols = 64;  cl -= WC_L3; }
        int q = cl & 3, rest = cl >> 2;
        int n = rest % Ncols, k08 = rest / Ncols;
        int kb = k08 * 16 + 2 * q + ((s & 1) ? 8 : 0);
        float v0 = Wsrc[kb * Ncols + n];
        float v1 = Wsrc[(kb + 1) * Ncols + n];
        unsigned short h0, l0, h1, l1;
        split_bf16(v0, h0, l0);
        split_bf16(v1, h1, l1);
        uint32_t w = (s < 2) ? ((uint32_t)h0 | ((uint32_t)h1 << 16))
                             : ((uint32_t)l0 | ((uint32_t)l1 << 16));
        ((uint32_t*)g_Wint)[i] = w;
    }

    if (i < NN * 32) {                               // x: one float4 -> 4 bf16
        float4 v = ((const float4*)x)[i];
        __nv_bfloat16 b0 = __float2bfloat16(v.x), b1 = __float2bfloat16(v.y);
        __nv_bfloat16 b2 = __float2bfloat16(v.z), b3 = __float2bfloat16(v.w);
        uint2 u;
        u.x = (uint32_t)__bfloat16_as_ushort(b0) | ((uint32_t)__bfloat16_as_ushort(b1) << 16);
        u.y = (uint32_t)__bfloat16_as_ushort(b2) | ((uint32_t)__bfloat16_as_ushort(b3) << 16);
        ((uint2*)g_Xb)[i] = u;
    }
}

// ---------------- scan phase 1: block-local inclusive scan of (deg+1); self-zero deg ----------------
__global__ void k_scan1() {
    __shared__ int wsum[32];
    int t = threadIdx.x, lane = t & 31, w = t >> 5;
    int idx = blockIdx.x * SCAN_BLK + t;
    int v = 0;
    if (idx < NN) {
        int d = g_deg[idx];
        g_deg[idx] = 0;                      // reset for next graph replay
        v = d + 1;                           // + self loop
        g_dinv[idx] = rsqrtf((float)v);
    }
    int x = v;
    #pragma unroll
    for (int o = 1; o < 32; o <<= 1) {
        int y = __shfl_up_sync(0xFFFFFFFFu, x, o);
        if (lane >= o) x += y;
    }
    if (lane == 31) wsum[w] = x;
    __syncthreads();
    if (w == 0) {
        int s = wsum[lane];
        #pragma unroll
        for (int o = 1; o < 32; o <<= 1) {
            int y = __shfl_up_sync(0xFFFFFFFFu, s, o);
            if (lane >= o) s += y;
        }
        wsum[lane] = s;
    }
    __syncthreads();
    int incl = x + (w > 0 ? wsum[w - 1] : 0);
    if (idx < NN) g_rowptr[idx + 1] = incl;
    if (t == SCAN_BLK - 1) g_bsum[blockIdx.x] = incl;
}

// scan phase 3 (with inlined phase-2 scan of 49 block sums) + cursor init
__global__ void k_scan3() {
    __shared__ int sboff[SCAN_NBLK];
    int t = threadIdx.x;
    if (t < 32) {
        int i0 = 2 * t, i1 = 2 * t + 1;
        int e0 = (i0 < SCAN_NBLK) ? g_bsum[i0] : 0;
        int e1 = (i1 < SCAN_NBLK) ? g_bsum[i1] : 0;
        int p = e0 + e1, x = p;
        #pragma unroll
        for (int o = 1; o < 32; o <<= 1) {
            int y = __shfl_up_sync(0xFFFFFFFFu, x, o);
            if (t >= o) x += y;
        }
        int excl = x - p;
        if (i0 < SCAN_NBLK) sboff[i0] = excl;
        if (i1 < SCAN_NBLK) sboff[i1] = excl + e0;
    }
    __syncthreads();
    int i = blockIdx.x * blockDim.x + t;
    if (i >= NN) return;
    int r = g_rowptr[i + 1] + sboff[i >> 10];
    g_rowptr[i + 1] = r;
    if (i + 1 < NN) g_cursor[i + 1] = r;
    if (i == 0) { g_rowptr[0] = 0; g_cursor[0] = 0; }
}

// CSR fill, 4 edges per thread (batched independent atomic chains, MLP=4)
__global__ void k_fill_csr(const int* __restrict__ src, const int* __restrict__ dst) {
    int base = (blockIdx.x * blockDim.x + threadIdx.x) * 4;
    if (base >= NEL) return;

    int s[4], d[4];
    bool ok[4];
    #pragma unroll
    for (int j = 0; j < 4; j++) {
        int i = base + j;
        ok[j] = (i < NEL);
        if (ok[j]) {
            if (i < NE) { s[j] = src[i]; d[j] = dst[i]; }
            else        { s[j] = d[j] = i - NE; }          // self loop
        }
    }
    float dvs[4], dvd[4];
    #pragma unroll
    for (int j = 0; j < 4; j++) {
        if (ok[j]) { dvs[j] = g_dinv[s[j]]; dvd[j] = g_dinv[d[j]]; }
    }
    int pos[4];
    #pragma unroll
    for (int j = 0; j < 4; j++) {
        if (ok[j]) pos[j] = atomicAdd(&g_cursor[d[j]], 1);
    }
    #pragma unroll
    for (int j = 0; j < 4; j++) {
        if (ok[j]) g_csr[pos[j]] = make_int2(s[j], __float_as_int(dvs[j] * dvd[j]));
    }
}

// ---------------- CSR gather-aggregation: G[node] = sum_e norm_e * X[src_e]  (bf16 in/out) ----------------
__global__ __launch_bounds__(256)
void k_agg(const __nv_bfloat16* __restrict__ X) {
    int t = threadIdx.x, ln = t & 31;
    int node = blockIdx.x * 8 + (t >> 5);
    if (node >= NN) return;

    int beg = g_rowptr[node], end = g_rowptr[node + 1];
    float4 acc = make_float4(0.f, 0.f, 0.f, 0.f);

    int e = beg;
    for (; e + 4 <= end; e += 4) {
        int2 m0 = g_csr[e + 0], m1 = g_csr[e + 1];
        int2 m2 = g_csr[e + 2], m3 = g_csr[e + 3];
        uint2 u0 = ((const uint2*)(X + (size_t)m0.x * 128))[ln];
        uint2 u1 = ((const uint2*)(X + (size_t)m1.x * 128))[ln];
        uint2 u2 = ((const uint2*)(X + (size_t)m2.x * 128))[ln];
        uint2 u3 = ((const uint2*)(X + (size_t)m3.x * 128))[ln];
        float w0 = __int_as_float(m0.y), w1 = __int_as_float(m1.y);
        float w2 = __int_as_float(m2.y), w3 = __int_as_float(m3.y);
        float2 a0 = __bfloat1622float2(*(__nv_bfloat162*)&u0.x);
        float2 b0 = __bfloat1622float2(*(__nv_bfloat162*)&u0.y);
        float2 a1 = __bfloat1622float2(*(__nv_bfloat162*)&u1.x);
        float2 b1 = __bfloat1622float2(*(__nv_bfloat162*)&u1.y);
        float2 a2 = __bfloat1622float2(*(__nv_bfloat162*)&u2.x);
        float2 b2 = __bfloat1622float2(*(__nv_bfloat162*)&u2.y);
        float2 a3 = __bfloat1622float2(*(__nv_bfloat162*)&u3.x);
        float2 b3 = __bfloat1622float2(*(__nv_bfloat162*)&u3.y);
        acc.x = fmaf(w0, a0.x, acc.x); acc.y = fmaf(w0, a0.y, acc.y);
        acc.z = fmaf(w0, b0.x, acc.z); acc.w = fmaf(w0, b0.y, acc.w);
        acc.x = fmaf(w1, a1.x, acc.x); acc.y = fmaf(w1, a1.y, acc.y);
        acc.z = fmaf(w1, b1.x, acc.z); acc.w = fmaf(w1, b1.y, acc.w);
        acc.x = fmaf(w2, a2.x, acc.x); acc.y = fmaf(w2, a2.y, acc.y);
        acc.z = fmaf(w2, b2.x, acc.z); acc.w = fmaf(w2, b2.y, acc.w);
        acc.x = fmaf(w3, a3.x, acc.x); acc.y = fmaf(w3, a3.y, acc.y);
        acc.z = fmaf(w3, b3.x, acc.z); acc.w = fmaf(w3, b3.y, acc.w);
    }
    for (; e < end; e++) {
        int2 m = g_csr[e];
        uint2 u = ((const uint2*)(X + (size_t)m.x * 128))[ln];
        float w = __int_as_float(m.y);
        float2 a = __bfloat1622float2(*(__nv_bfloat162*)&u.x);
        float2 b = __bfloat1622float2(*(__nv_bfloat162*)&u.y);
        acc.x = fmaf(w, a.x, acc.x); acc.y = fmaf(w, a.y, acc.y);
        acc.z = fmaf(w, b.x, acc.z); acc.w = fmaf(w, b.y, acc.w);
    }

    __nv_bfloat16 o0 = __float2bfloat16(acc.x), o1 = __float2bfloat16(acc.y);
    __nv_bfloat16 o2 = __float2bfloat16(acc.z), o3 = __float2bfloat16(acc.w);
    uint2 u;
    u.x = (uint32_t)__bfloat16_as_ushort(o0) | ((uint32_t)__bfloat16_as_ushort(o1) << 16);
    u.y = (uint32_t)__bfloat16_as_ushort(o2) | ((uint32_t)__bfloat16_as_ushort(o3) << 16);
    ((uint2*)(g_G + (size_t)node * 128))[ln] = u;
}

// ================= HMMA bf16 m16n8k16 =================
__device__ __forceinline__ void mma_bf16(float* c, const uint32_t* a, uint32_t b0, uint32_t b1) {
    asm volatile(
        "mma.sync.aligned.m16n8k16.row.col.f32.bf16.bf16.f32 "
        "{%0,%1,%2,%3}, {%4,%5,%6,%7}, {%8,%9}, {%0,%1,%2,%3};"
        : "+f"(c[0]), "+f"(c[1]), "+f"(c[2]), "+f"(c[3])
        : "r"(a[0]), "r"(a[1]), "r"(a[2]), "r"(a[3]), "r"(b0), "r"(b1));
}

// ====== GEMM + fused epilogue: Out = relu(G[M x 128] @ (Whi+Wlo)T + b), 2-pass compensated ======
// 256 thr = 8 warps; block tile 128 x N. W pre-interleaved: chunk[(k08*N+n)*4+q] = {b0hi,b1hi,b0lo,b1lo}.
template <int N, bool F32OUT>
__global__ __launch_bounds__(256)
void k_gemm(const __nv_bfloat16* __restrict__ G, const uint4* __restrict__ Wc,
            const float* __restrict__ bias, void* __restrict__ Out) {
    constexpr int NT = N / 8;
    constexpr int NCH = 32 * N;                // chunks: 8*N*4
    extern __shared__ uint4 sW[];

    int tid = threadIdx.x, wid = tid >> 5, lane = tid & 31;

    #pragma unroll
    for (int i = tid; i < NCH; i += 256) sW[i] = Wc[i];
    __syncthreads();

    int row0 = blockIdx.x * 128 + wid * 16;
    int grp = lane >> 2;                       // 0..7
    int q   = lane & 3;
    int qk  = q * 2;

    float acc[NT][4];
    #pragma unroll
    for (int j = 0; j < NT; j++)
        #pragma unroll
        for (int p = 0; p < 4; p++) acc[j][p] = 0.f;

    #pragma unroll
    for (int k08 = 0; k08 < 8; k08++) {
        size_t ab = (size_t)(row0 + grp) * 128 + k08 * 16 + qk;
        uint32_t a[4];
        a[0] = *(const uint32_t*)(G + ab);
        a[1] = *(const uint32_t*)(G + ab + 8 * 128);
        a[2] = *(const uint32_t*)(G + ab + 8);
        a[3] = *(const uint32_t*)(G + ab + 8 * 128 + 8);

        #pragma unroll
        for (int j = 0; j < NT; j++) {
            uint4 bb = sW[(k08 * N + j * 8 + grp) * 4 + q];   // one LDS.128
            mma_bf16(acc[j], a, bb.x, bb.y);   // A * W_hi
            mma_bf16(acc[j], a, bb.z, bb.w);   // A * W_lo
        }
    }

    int rc = row0 + grp;
    int cc = (lane & 3) * 2;
    #pragma unroll
    for (int j = 0; j < NT; j++) {
        int col = j * 8 + cc;
        float bx = bias[col], by = bias[col + 1];
        float v0 = fmaxf(acc[j][0] + bx, 0.f), v1 = fmaxf(acc[j][1] + by, 0.f);
        float v2 = fmaxf(acc[j][2] + bx, 0.f), v3 = fmaxf(acc[j][3] + by, 0.f);
        if (F32OUT) {
            float* O = (float*)Out;
            if (rc < NN)     *(float2*)&O[(size_t)rc * N + col]       = make_float2(v0, v1);
            if (rc + 8 < NN) *(float2*)&O[(size_t)(rc + 8) * N + col] = make_float2(v2, v3);
        } else {
            __nv_bfloat16* O = (__nv_bfloat16*)Out;
            if (rc < NN) {
                __nv_bfloat162 h = __floats2bfloat162_rn(v0, v1);
                *(uint32_t*)&O[(size_t)rc * N + col] = *(uint32_t*)&h;
            }
            if (rc + 8 < NN) {
                __nv_bfloat162 h = __floats2bfloat162_rn(v2, v3);
                *(uint32_t*)&O[(size_t)(rc + 8) * N + col] = *(uint32_t*)&h;
            }
        }
    }
}

// ---------------- fused mean-pool (batch is sorted) + MLP head ----------------
__device__ __forceinline__ int lower_bound_batch(const int* __restrict__ batch, int key) {
    int lo = 0, hi = NN;
    while (lo < hi) {
        int mid = (lo + hi) >> 1;
        if (batch[mid] < key) lo = mid + 1; else hi = mid;
    }
    return lo;
}

__global__ __launch_bounds__(256)
void k_pool_mlp(const float* __restrict__ A, const int* __restrict__ batch,
                const float* __restrict__ demo,
                const float* __restrict__ Wf1, const float* __restrict__ bf1,
                const float* __restrict__ Wf2, const float* __restrict__ bf2,
                const float* __restrict__ Wf3, const float* __restrict__ bf3,
                float* __restrict__ out) {
    int g = blockIdx.x;
    int t = threadIdx.x;
    __shared__ int s_beg, s_end;
    __shared__ float sp[4][64];
    __shared__ float z[72];
    __shared__ float z1[64];
    __shared__ float z2[32];

    if (t == 0) s_beg = lower_bound_batch(batch, g);
    if (t == 1) s_end = lower_bound_batch(batch, g + 1);
    __syncthreads();
    int beg = s_beg, end = s_end;

    int c = t & 63, rg = t >> 6;
    float acc = 0.f;
    for (int r = beg + rg; r < end; r += 4)
        acc += A[(size_t)r * OUTC + c];
    sp[rg][c] = acc;
    __syncthreads();

    if (t < 64) {
        float s = sp[0][t] + sp[1][t] + sp[2][t] + sp[3][t];
        float invc = 1.f / fmaxf((float)(end - beg), 1.f);
        z[t] = s * invc;
    }
    if (t < DEMO) z[64 + t] = demo[g * DEMO + t];
    __syncthreads();

    if (t < 64) {
        float a = bf1[t];
        #pragma unroll 8
        for (int k = 0; k < 72; k++) a += z[k] * Wf1[k * 64 + t];
        z1[t] = fmaxf(a, 0.f);
    }
    __syncthreads();
    if (t < 32) {
        float a = bf2[t];
        #pragma unroll 8
        for (int k = 0; k < 64; k++) a += z1[k] * Wf2[k * 32 + t];
        z2[t] = fmaxf(a, 0.f);
    }
    __syncthreads();
    if (t < 2) {
        float a = bf3[t];
        #pragma unroll
        for (int k = 0; k < 32; k++) a += z2[k] * Wf3[k * 2 + t];
        out[g * 2 + t] = a;
    }
}

// ---------------- launch ----------------
extern "C" void kernel_launch(void* const* d_in, const int* in_sizes, int n_in,
                              void* d_out, int out_size) {
    const float* x     = (const float*)d_in[0];
    const int*   ei    = (const int*)  d_in[1];   // [2, NE]
    const int*   batch = (const int*)  d_in[2];
    const float* demo  = (const float*)d_in[3];
    const float* W1 = (const float*)d_in[4];  const float* b1 = (const float*)d_in[5];
    const float* W2 = (const float*)d_in[6];  const float* b2 = (const float*)d_in[7];
    const float* W3 = (const float*)d_in[8];  const float* b3 = (const float*)d_in[9];
    const float* Wf1 = (const float*)d_in[10]; const float* bf1 = (const float*)d_in[11];
    const float* Wf2 = (const float*)d_in[12]; const float* bf2 = (const float*)d_in[13];
    const float* Wf3 = (const float*)d_in[14]; const float* bf3 = (const float*)d_in[15];
    float* out = (float*)d_out;

    const int* src = ei;
    const int* dst = ei + NE;

    float* A;
    __nv_bfloat16 *Xb, *Ab, *G;
    uint4* Wc;
    cudaGetSymbolAddress((void**)&A,  g_A);
    cudaGetSymbolAddress((void**)&Xb, g_Xb);
    cudaGetSymbolAddress((void**)&Ab, g_Ab);
    cudaGetSymbolAddress((void**)&G,  g_G);
    cudaGetSymbolAddress((void**)&Wc, g_Wint);

    const int SMEM128 = 32 * 128 * 16;   // 65536
    const int SMEM64  = 32 * 64  * 16;   // 32768
    cudaFuncSetAttribute(k_gemm<128, false>, cudaFuncAttributeMaxDynamicSharedMemorySize, SMEM128);
    cudaFuncSetAttribute(k_gemm<64,  true>,  cudaFuncAttributeMaxDynamicSharedMemorySize, SMEM64);

    const int T = 256;
    // --- fused prep (deg atomics + x->bf16 + W interleave) ---
    k_prep<<<(NN * 32 + T - 1) / T, T>>>(x, W1, W2, W3, dst);
    // --- CSR build ---
    k_scan1<<<SCAN_NBLK, SCAN_BLK>>>();
    k_scan3<<<(NN + T - 1) / T, T>>>();
    k_fill_csr<<<(NEL / 4 + T) / T, T>>>(src, dst);

    const int AGG_GRID = (NN + 7) / 8;
    // --- layer 1: G = S @ Xb ; Ab = relu(G @ W1 + b1) ---
    k_agg<<<AGG_GRID, 256>>>(Xb);
    k_gemm<128, false><<<NTILES, 256, SMEM128>>>(G, Wc, b1, Ab);
    // --- layer 2 ---
    k_agg<<<AGG_GRID, 256>>>(Ab);
    k_gemm<128, false><<<NTILES, 256, SMEM128>>>(G, Wc + WC_L2, b2, Ab);
    // --- layer 3 (N=64, fp32 out) ---
    k_agg<<<AGG_GRID, 256>>>(Ab);
    k_gemm<64, true><<<NTILES, 256, SMEM64>>>(G, Wc + WC_L3, b3, A);

    // --- fused pooling + MLP head ---
    k_pool_mlp<<<NG, 256>>>(A, batch, demo, Wf1, bf1, Wf2, bf2, Wf3, bf3, out);
}